// round 9
// baseline (speedup 1.0000x reference)
#include <cuda_runtime.h>
#include <math.h>

// Problem constants
#define B_  16
#define NN  4096
#define D_  64
#define O_  12
#define S_  32
#define M_  12
#define A_  32

// Output layout: H_time [B,O,N,D] ++ attn [B,O,N,M] ++ gate [B,O,M]
#define ATT_OFF  50331648ull
#define GATE_OFF 59768832ull
#define SCALE 0.17677669529663688f   // 1/sqrt(32)

#define QSTRIDE 36   // floats per qh row: 9x16B -> LDS.128-aligned & conflict-free

// Scratch
__device__ float g_Q[(size_t)B_*NN*A_]; // [b][n][a]

typedef unsigned long long ull;

__device__ __forceinline__ ull ffma2(ull a, ull b, ull c) {
    ull d;
    asm("fma.rn.f32x2 %0, %1, %2, %3;" : "=l"(d) : "l"(a), "l"(b), "l"(c));
    return d;
}
__device__ __forceinline__ ull pack2(float x, float y) {
    ull r;
    asm("mov.b64 %0, {%1, %2};" : "=l"(r) : "r"(__float_as_uint(x)), "r"(__float_as_uint(y)));
    return r;
}
__device__ __forceinline__ float2 unpack2(ull v) {
    unsigned int lo, hi;
    asm("mov.b64 {%0, %1}, %2;" : "=r"(lo), "=r"(hi) : "l"(v));
    return make_float2(__uint_as_float(lo), __uint_as_float(hi));
}

// ============================================================================
// Kernel 1: qh[b,n,a] = H[b,n,:] . Wq[a,:D]   (thread per n)
// ============================================================================
__global__ __launch_bounds__(128)
void qh_kernel(const float* __restrict__ H, const float* __restrict__ Wq) {
    __shared__ float wq_sh[A_ * D_];   // [a][d]
    const int b   = blockIdx.y;
    const int tid = threadIdx.x;
    const int n   = blockIdx.x * 128 + tid;

    for (int i = tid; i < A_ * D_; i += 128)
        wq_sh[i] = Wq[(i >> 6) * (D_ + S_) + (i & 63)];
    __syncthreads();

    const float4* Hrow = (const float4*)(H + ((size_t)b * NN + n) * D_);
    ull hp[D_ / 2];
    #pragma unroll
    for (int i = 0; i < D_ / 4; i++) {
        float4 v = Hrow[i];
        hp[2 * i]     = pack2(v.x, v.y);
        hp[2 * i + 1] = pack2(v.z, v.w);
    }
    float qh[A_];
    #pragma unroll
    for (int a = 0; a < A_; a++) {
        ull acc = 0ull;
        const ulonglong2* wr = (const ulonglong2*)(wq_sh + a * D_);
        #pragma unroll
        for (int j = 0; j < D_ / 4; j++) {
            ulonglong2 w = wr[j];
            acc = ffma2(hp[2 * j],     w.x, acc);
            acc = ffma2(hp[2 * j + 1], w.y, acc);
        }
        float2 f = unpack2(acc);
        qh[a] = f.x + f.y;
    }
    float4* Qo = (float4*)(g_Q + ((size_t)b * NN + n) * A_);
    #pragma unroll
    for (int ac = 0; ac < A_ / 4; ac++)
        Qo[ac] = make_float4(qh[4*ac], qh[4*ac+1], qh[4*ac+2], qh[4*ac+3]);
}

// ============================================================================
// Kernel 2: main. Block = 64 n x 6 o (o-half), 256 threads.
// Inline precompute of key/val/c/qs from raw inputs (scratch lives in at_sh).
//   smem (floats): key 2304 | val 4608 | c 72 | at 4608 | qh 64*36=2304
// ============================================================================
#define SMEM_FLOATS 13896

__global__ __launch_bounds__(256, 4)
void attn_kernel(const float* __restrict__ H,
                 const float* __restrict__ ts_out,
                 const float* __restrict__ step_emb,
                 const float* __restrict__ key_emb,
                 const float* __restrict__ val_emb,
                 const float* __restrict__ Wk,
                 const float* __restrict__ Wg,
                 const float* __restrict__ bg,
                 const float* __restrict__ bq,
                 const float* __restrict__ Wq,
                 float* __restrict__ out) {
    extern __shared__ float sh[];
    float* key_sh = sh;             // [ol][a][m]  2304
    float* val_sh = sh + 2304;      // [ol][m][d]  4608
    float* c_sh   = sh + 6912;      // [ol][m] 72  (phase 0: Wk scratch, 64)
    float* at_sh  = sh + 6984;      // [ol*64+nl][m] 4608 (pre-A: precompute scratch)
    float* qh_sh  = sh + 11592;     // [nl][a] stride QSTRIDE (pre-A: Wq[:,D:] [a][s])

    const int t   = threadIdx.x;
    const int b   = blockIdx.z;
    const int oh  = blockIdx.y;
    const int n0  = blockIdx.x * 64;
    const int ob0 = b * O_ + oh * 6;

    // precompute scratch inside at_sh
    float* step_s = at_sh;          // [ol][s]  192
    float* tok_s  = at_sh + 192;    // [ol][2m] 144
    float* gate_s = at_sh + 336;    // [ol][m]  72
    float* qs_s   = at_sh + 408;    // [ol][a]  192

    // ---- phase 0: stage Wq[:,D:] (stride QSTRIDE), step_emb, Wk ----
    for (int i = t; i < 1024; i += 256)
        qh_sh[(i >> 5) * QSTRIDE + (i & 31)] = Wq[(i >> 5) * (D_ + S_) + D_ + (i & 31)];
    if (t < 192) step_s[t] = step_emb[(ob0 + (t >> 5)) * S_ + (t & 31)];
    if (t >= 192) c_sh[t - 192] = Wk[t - 192];   // 64 floats of Wk
    __syncthreads();

    // ---- phase 1: fourier tokens + gate ----
    if (t < 72) {
        const int ol = t / 12, m = t - ol * 12;
        const float ph = (m < 8) ? ts_out[(ob0 + ol) * 2] : ts_out[(ob0 + ol) * 2 + 1];
        const int   k  = (m < 8) ? (m + 1) : (m - 7);
        const float ang = 6.283185307179586477f * ph * (float)k;
        float sn, cs;
        sincosf(ang, &sn, &cs);
        tok_s[2 * t]     = sn;      // = [ol*24 + 2m]
        tok_s[2 * t + 1] = cs;
        const float g = tanhf(sn * Wg[0] + cs * Wg[1] + bg[0]);
        gate_s[t] = g;
        if (blockIdx.x == 0)
            out[GATE_OFF + (size_t)ob0 * M_ + t] = g;
    }
    __syncthreads();

    // ---- phase 2: key, val, qs ----
    for (int i = t; i < 2304; i += 256) {
        const int ol = i / 384;
        const int r  = i - ol * 384;       // a*12 + m
        const int a  = r / 12, m = r - a * 12;
        key_sh[i] = tok_s[ol * 24 + 2 * m] * c_sh[2 * a]
                  + tok_s[ol * 24 + 2 * m + 1] * c_sh[2 * a + 1]
                  + key_emb[m * A_ + a];
    }
    for (int i = t; i < 4608; i += 256) {
        const int ol = i / 768;
        const int r  = i - ol * 768;       // m*64 + d
        val_sh[i] = gate_s[ol * 12 + (r >> 6)] * val_emb[r];
    }
    if (t < 192) {
        const int ol = t >> 5, a = t & 31;
        float acc = bq[a];
        #pragma unroll
        for (int s = 0; s < S_; s++)
            acc += step_s[ol * S_ + s] * qh_sh[a * QSTRIDE + s];
        qs_s[t] = acc;
    }
    __syncthreads();

    // ---- phase 3: c = qs.key ; stage Q -> qh_sh (overwrites Wq copy) ----
    {
        const float* Qb = g_Q + ((size_t)b * NN + n0) * A_;
        for (int i = t; i < 2048; i += 256)
            qh_sh[(i >> 5) * QSTRIDE + (i & 31)] = Qb[i];
    }
    if (t < 72) {
        const int ol = t / 12, m = t - ol * 12;
        float acc = 0.f;
        const float* kk = key_sh + ol * 384 + m;
        const float* qq = qs_s + ol * A_;
        #pragma unroll
        for (int a = 0; a < A_; a++) acc += qq[a] * kk[a * 12];
        c_sh[t] = acc;
    }
    __syncthreads();

    // ---- phase A: job = (nl, ol); logits, softmax -> at_sh only ----
    for (int j = t; j < 384; j += 256) {
        const int nl = j & 63;
        const int ol = j >> 6;

        ull lg[6];
        const float* cp = c_sh + ol * M_;
        #pragma unroll
        for (int p = 0; p < 6; p++) lg[p] = pack2(cp[2 * p], cp[2 * p + 1]);

        // qh row via 8x LDS.128 (row base = nl*36 floats = nl*144 B, 16B-aligned)
        float qh[A_];
        {
            const float4* qp4 = (const float4*)(qh_sh + nl * QSTRIDE);
            #pragma unroll
            for (int q = 0; q < 8; q++) {
                float4 v = qp4[q];
                qh[4*q] = v.x; qh[4*q+1] = v.y; qh[4*q+2] = v.z; qh[4*q+3] = v.w;
            }
        }
        const float* kp = key_sh + ol * (A_ * M_);
        #pragma unroll
        for (int a = 0; a < A_; a++) {
            const ull q2 = pack2(qh[a], qh[a]);
            const ulonglong2* kr = (const ulonglong2*)(kp + a * M_);
            ulonglong2 k0 = kr[0], k1 = kr[1], k2 = kr[2];
            lg[0] = ffma2(q2, k0.x, lg[0]);
            lg[1] = ffma2(q2, k0.y, lg[1]);
            lg[2] = ffma2(q2, k1.x, lg[2]);
            lg[3] = ffma2(q2, k1.y, lg[3]);
            lg[4] = ffma2(q2, k2.x, lg[4]);
            lg[5] = ffma2(q2, k2.y, lg[5]);
        }
        float l[M_];
        #pragma unroll
        for (int p = 0; p < 6; p++) {
            float2 f = unpack2(lg[p]);
            l[2 * p] = f.x; l[2 * p + 1] = f.y;
        }
        float mx = l[0];
        #pragma unroll
        for (int m = 1; m < M_; m++) mx = fmaxf(mx, l[m]);
        float ssum = 0.f, at[M_];
        #pragma unroll
        for (int m = 0; m < M_; m++) {
            const float e = __expf((l[m] - mx) * SCALE);
            at[m] = e; ssum += e;
        }
        const float inv = __frcp_rn(ssum);
        #pragma unroll
        for (int m = 0; m < M_; m++) at[m] *= inv;

        float4* as = (float4*)(at_sh + (ol * 64 + nl) * M_);
        as[0] = make_float4(at[0], at[1], at[2],  at[3]);
        as[1] = make_float4(at[4], at[5], at[6],  at[7]);
        as[2] = make_float4(at[8], at[9], at[10], at[11]);
    }
    __syncthreads();

    // ---- attn output: coalesced copy at_sh -> global ----
    if (t < 192) {
        #pragma unroll
        for (int ol = 0; ol < 6; ol++) {
            float4 v = *(const float4*)(at_sh + ol * 768 + t * 4);
            *(float4*)(out + ATT_OFF + ((size_t)(ob0 + ol) * NN + n0) * M_ + t * 4) = v;
        }
    }

    // ---- phase B: thread = (dq2 8B-chunk, nn0); val hoisted per o ----
    const int dq2 = t & 31;
    const int nn0 = t >> 5;
    const ull ALPHA2 = pack2(0.1f, 0.1f);

    ull hh[8];
    #pragma unroll
    for (int p = 0; p < 8; p++)
        hh[p] = *(const ull*)(H + ((size_t)b * NN + n0 + p * 8 + nn0) * D_ + dq2 * 2);

    #pragma unroll 1
    for (int ol = 0; ol < 6; ol++) {
        ull vv[M_];
        const float* vb = val_sh + ol * (M_ * D_) + dq2 * 2;
        #pragma unroll
        for (int m = 0; m < M_; m++) vv[m] = *(const ull*)(vb + m * D_);

        const float* atb = at_sh + ol * 64 * M_;
        float* ob = out + ((size_t)(ob0 + ol) * NN + n0) * D_ + dq2 * 2;
        #pragma unroll
        for (int p = 0; p < 8; p++) {
            const int nn = p * 8 + nn0;
            const float4* ap = (const float4*)(atb + nn * M_);
            float4 u0 = ap[0], u1 = ap[1], u2 = ap[2];
            ull acc = 0ull;
            acc = ffma2(pack2(u0.x, u0.x), vv[0],  acc);
            acc = ffma2(pack2(u0.y, u0.y), vv[1],  acc);
            acc = ffma2(pack2(u0.z, u0.z), vv[2],  acc);
            acc = ffma2(pack2(u0.w, u0.w), vv[3],  acc);
            acc = ffma2(pack2(u1.x, u1.x), vv[4],  acc);
            acc = ffma2(pack2(u1.y, u1.y), vv[5],  acc);
            acc = ffma2(pack2(u1.z, u1.z), vv[6],  acc);
            acc = ffma2(pack2(u1.w, u1.w), vv[7],  acc);
            acc = ffma2(pack2(u2.x, u2.x), vv[8],  acc);
            acc = ffma2(pack2(u2.y, u2.y), vv[9],  acc);
            acc = ffma2(pack2(u2.z, u2.z), vv[10], acc);
            acc = ffma2(pack2(u2.w, u2.w), vv[11], acc);
            *(ull*)(ob + (size_t)nn * D_) = ffma2(acc, ALPHA2, hh[p]);
        }
    }
}

// ============================================================================
extern "C" void kernel_launch(void* const* d_in, const int* in_sizes, int n_in,
                              void* d_out, int out_size) {
    const float* H        = (const float*)d_in[0];
    const float* ts_out   = (const float*)d_in[1];
    const float* step_emb = (const float*)d_in[2];
    const float* key_emb  = (const float*)d_in[3];
    const float* val_emb  = (const float*)d_in[4];
    const float* Wk       = (const float*)d_in[5];
    const float* Wg       = (const float*)d_in[6];
    const float* bg       = (const float*)d_in[7];
    const float* Wq       = (const float*)d_in[8];
    const float* bq       = (const float*)d_in[9];
    float* out = (float*)d_out;

    qh_kernel<<<dim3(NN / 128, B_), 128>>>(H, Wq);

    const int smem_bytes = SMEM_FLOATS * 4;  // 55584 B
    cudaFuncSetAttribute(attn_kernel, cudaFuncAttributeMaxDynamicSharedMemorySize,
                         smem_bytes);
    attn_kernel<<<dim3(NN / 64, 2, B_), 256, smem_bytes>>>(
        H, ts_out, step_emb, key_emb, val_emb, Wk, Wg, bg, bq, Wq, out);
}

// round 11
// speedup vs baseline: 1.1711x; 1.1711x over previous
#include <cuda_runtime.h>
#include <math.h>

// Problem constants
#define B_  16
#define NN  4096
#define D_  64
#define O_  12
#define S_  32
#define M_  12
#define A_  32

// Output layout: H_time [B,O,N,D] ++ attn [B,O,N,M] ++ gate [B,O,M]
#define ATT_OFF  50331648ull
#define GATE_OFF 59768832ull
#define SCALE 0.17677669529663688f   // 1/sqrt(32)

#define QSTRIDE 36   // qh row stride in floats: 9x16B -> LDS.128-aligned, conflict-free

// Scratch
__device__ float g_key[B_*O_*A_*M_];      // [b][o][a][m]
__device__ float g_val[B_*O_*M_*D_];      // [b][o][m][d]  (gate folded in)
__device__ float g_c  [B_*O_*M_];         // [b][o][m]     (qs . key)
__device__ float g_Q  [(size_t)B_*NN*A_]; // [b][n][a]

typedef unsigned long long ull;

__device__ __forceinline__ ull ffma2(ull a, ull b, ull c) {
    ull d;
    asm("fma.rn.f32x2 %0, %1, %2, %3;" : "=l"(d) : "l"(a), "l"(b), "l"(c));
    return d;
}
__device__ __forceinline__ ull pack2(float x, float y) {
    ull r;
    asm("mov.b64 %0, {%1, %2};" : "=l"(r) : "r"(__float_as_uint(x)), "r"(__float_as_uint(y)));
    return r;
}
__device__ __forceinline__ float2 unpack2(ull v) {
    unsigned int lo, hi;
    asm("mov.b64 {%0, %1}, %2;" : "=r"(lo), "=r"(hi) : "l"(v));
    return make_float2(__uint_as_float(lo), __uint_as_float(hi));
}

// ============================================================================
// Kernel 1 (fused prep): bx<32 -> qh (split-D, 2 threads/n); bx==32 -> precompute
// ============================================================================
__global__ __launch_bounds__(256)
void prep_kernel(const float* __restrict__ H,
                 const float* __restrict__ ts_out,
                 const float* __restrict__ step_emb,
                 const float* __restrict__ key_emb,
                 const float* __restrict__ val_emb,
                 const float* __restrict__ Wk,
                 const float* __restrict__ Wg,
                 const float* __restrict__ bg,
                 const float* __restrict__ bq,
                 const float* __restrict__ Wq,
                 float* __restrict__ out) {
    __shared__ float ps[2560];
    const int b = blockIdx.y;
    const int t = threadIdx.x;

    if (blockIdx.x < 32) {
        // ---------------- qh: 2 threads per n, split D ----------------
        // wq layout: [a] stride 72 floats; half0 at +0 (d=0..31), half1 at +36 (d=32..63)
        for (int i = t; i < 2048; i += 256) {
            const int a = i >> 6, d = i & 63;
            ps[a * 72 + ((d >= 32) ? (4 + d) : d)] = Wq[a * (D_ + S_) + d];
        }
        __syncthreads();

        const int nl   = t >> 1;
        const int half = t & 1;
        const int n    = blockIdx.x * 128 + nl;

        // H half-row: 32 floats -> 16 packed pairs
        const float4* Hp = (const float4*)(H + ((size_t)b * NN + n) * D_ + half * 32);
        ull hp[16];
        #pragma unroll
        for (int i = 0; i < 8; i++) {
            float4 v = Hp[i];
            hp[2 * i]     = pack2(v.x, v.y);
            hp[2 * i + 1] = pack2(v.z, v.w);
        }

        float qh[A_];
        #pragma unroll
        for (int a = 0; a < A_; a++) {
            const ulonglong2* wr = (const ulonglong2*)(ps + a * 72 + half * 36);
            ull acc = 0ull;
            #pragma unroll
            for (int j = 0; j < 8; j++) {           // pairs (2j, 2j+1) of this half
                ulonglong2 w = wr[j];
                acc = ffma2(hp[2 * j],     w.x, acc);
                acc = ffma2(hp[2 * j + 1], w.y, acc);
            }
            float2 f = unpack2(acc);
            const float part = f.x + f.y;
            qh[a] = part + __shfl_xor_sync(0xffffffffu, part, 1);
        }

        // even thread stores a[0..15], odd stores a[16..31] -> warp = 4KB contiguous
        float4* Qo = (float4*)(g_Q + ((size_t)b * NN + n) * A_) + half * 4;
        #pragma unroll
        for (int g = 0; g < 4; g++) {
            const int a0 = half * 16 + g * 4;
            Qo[g] = make_float4(qh[a0], qh[a0 + 1], qh[a0 + 2], qh[a0 + 3]);
        }
    } else {
        // ---------------- precompute: all 12 o's for this b ----------------
        float* wqs    = ps;           // [a][s] 1024
        float* key_s  = ps + 1024;    // 384
        float* tok_s  = ps + 1408;    // 24
        float* gate_s = ps + 1432;    // 12
        float* qs_s   = ps + 1444;    // 32
        float* step_s = ps + 1476;    // 32

        for (int i = t; i < A_ * S_; i += 256)
            wqs[i] = Wq[(i >> 5) * (D_ + S_) + D_ + (i & 31)];
        __syncthreads();

        for (int o = 0; o < O_; o++) {
            const int bx = b * O_ + o;
            if (t < M_) {
                const int m = t;
                const float ph = (m < 8) ? ts_out[bx * 2] : ts_out[bx * 2 + 1];
                const int   k  = (m < 8) ? (m + 1) : (m - 7);
                const float ang = 6.283185307179586477f * ph * (float)k;
                float sn, cs;
                sincosf(ang, &sn, &cs);
                tok_s[2 * m]     = sn;
                tok_s[2 * m + 1] = cs;
                const float g = tanhf(sn * Wg[0] + cs * Wg[1] + bg[0]);
                gate_s[m] = g;
                out[GATE_OFF + (size_t)bx * M_ + m] = g;
            }
            if (t >= 32 && t < 64) step_s[t - 32] = step_emb[bx * S_ + t - 32];
            __syncthreads();

            for (int i = t; i < A_ * M_; i += 256) {
                const int a = i / 12, m = i - a * 12;
                const float kv = tok_s[2 * m] * Wk[2 * a] + tok_s[2 * m + 1] * Wk[2 * a + 1]
                               + key_emb[m * A_ + a];
                key_s[i] = kv;
                g_key[(size_t)bx * (A_ * M_) + i] = kv;
            }
            for (int i = t; i < M_ * D_; i += 256)
                g_val[(size_t)bx * (M_ * D_) + i] = gate_s[i >> 6] * val_emb[i];
            if (t < A_) {
                float acc = bq[t];
                #pragma unroll
                for (int s = 0; s < S_; s++) acc += step_s[s] * wqs[t * S_ + s];
                qs_s[t] = acc;
            }
            __syncthreads();

            if (t < M_) {
                float acc = 0.f;
                #pragma unroll
                for (int a = 0; a < A_; a++) acc += qs_s[a] * key_s[a * 12 + t];
                g_c[(size_t)bx * M_ + t] = acc;
            }
            __syncthreads();
        }
    }
}

// ============================================================================
// Kernel 2: main. Block = 64 n x 6 o (o-half), 256 threads.
//   smem (floats): key 2304 | val 4608 | c 72 | at 4608 | qh 64*36=2304
// ============================================================================
#define SMEM_FLOATS 13896

__global__ __launch_bounds__(256, 4)
void attn_kernel(const float* __restrict__ H, float* __restrict__ out) {
    extern __shared__ float sh[];
    float* key_sh = sh;             // [ol][a][m]  2304
    float* val_sh = sh + 2304;      // [ol][m][d]  4608
    float* c_sh   = sh + 6912;      // [ol][m] 72
    float* at_sh  = sh + 6984;      // [ol*64+nl][m] 4608
    float* qh_sh  = sh + 11592;     // [nl][a] stride QSTRIDE

    const int t   = threadIdx.x;
    const int b   = blockIdx.z;
    const int oh  = blockIdx.y;
    const int n0  = blockIdx.x * 64;
    const int ob0 = b * O_ + oh * 6;

    // ---- stage tables (coalesced) ----
    {
        const float4* gk = (const float4*)(g_key + (size_t)ob0 * (A_ * M_));
        float4* k4 = (float4*)key_sh;
        for (int i = t; i < 576; i += 256) k4[i] = gk[i];
        const float4* gv = (const float4*)(g_val + (size_t)ob0 * (M_ * D_));
        float4* v4 = (float4*)val_sh;
        for (int i = t; i < 1152; i += 256) v4[i] = gv[i];
        if (t < 72) c_sh[t] = g_c[(size_t)ob0 * M_ + t];
        // Q tile via float4: row = i>>3, col4 = i&7
        const float4* Qb = (const float4*)(g_Q + ((size_t)b * NN + n0) * A_);
        for (int i = t; i < 512; i += 256) {
            float4 v = Qb[i];
            *(float4*)(qh_sh + (i >> 3) * QSTRIDE + (i & 7) * 4) = v;
        }
    }
    __syncthreads();

    // ---- phase A: job = (nl, ol); logits, softmax -> at_sh ----
    for (int j = t; j < 384; j += 256) {
        const int nl = j & 63;
        const int ol = j >> 6;

        ull lg[6];
        const float* cp = c_sh + ol * M_;
        #pragma unroll
        for (int p = 0; p < 6; p++) lg[p] = pack2(cp[2 * p], cp[2 * p + 1]);

        float qh[A_];
        {
            const float4* qp4 = (const float4*)(qh_sh + nl * QSTRIDE);
            #pragma unroll
            for (int q = 0; q < 8; q++) {
                float4 v = qp4[q];
                qh[4*q] = v.x; qh[4*q+1] = v.y; qh[4*q+2] = v.z; qh[4*q+3] = v.w;
            }
        }
        const float* kp = key_sh + ol * (A_ * M_);
        #pragma unroll
        for (int a = 0; a < A_; a++) {
            const ull q2 = pack2(qh[a], qh[a]);
            const ulonglong2* kr = (const ulonglong2*)(kp + a * M_);
            ulonglong2 k0 = kr[0], k1 = kr[1], k2 = kr[2];
            lg[0] = ffma2(q2, k0.x, lg[0]);
            lg[1] = ffma2(q2, k0.y, lg[1]);
            lg[2] = ffma2(q2, k1.x, lg[2]);
            lg[3] = ffma2(q2, k1.y, lg[3]);
            lg[4] = ffma2(q2, k2.x, lg[4]);
            lg[5] = ffma2(q2, k2.y, lg[5]);
        }
        float l[M_];
        #pragma unroll
        for (int p = 0; p < 6; p++) {
            float2 f = unpack2(lg[p]);
            l[2 * p] = f.x; l[2 * p + 1] = f.y;
        }
        float mx = l[0];
        #pragma unroll
        for (int m = 1; m < M_; m++) mx = fmaxf(mx, l[m]);
        float ssum = 0.f, at[M_];
        #pragma unroll
        for (int m = 0; m < M_; m++) {
            const float e = __expf((l[m] - mx) * SCALE);
            at[m] = e; ssum += e;
        }
        const float inv = __frcp_rn(ssum);
        #pragma unroll
        for (int m = 0; m < M_; m++) at[m] *= inv;

        float4* as = (float4*)(at_sh + (ol * 64 + nl) * M_);
        as[0] = make_float4(at[0], at[1], at[2],  at[3]);
        as[1] = make_float4(at[4], at[5], at[6],  at[7]);
        as[2] = make_float4(at[8], at[9], at[10], at[11]);
    }
    __syncthreads();

    // ---- attn output: coalesced copy at_sh -> global ----
    if (t < 192) {
        #pragma unroll
        for (int ol = 0; ol < 6; ol++) {
            float4 v = *(const float4*)(at_sh + ol * 768 + t * 4);
            *(float4*)(out + ATT_OFF + ((size_t)(ob0 + ol) * NN + n0) * M_ + t * 4) = v;
        }
    }

    // ---- phase B: thread = (dq2 8B-chunk, nn0); val hoisted per o ----
    const int dq2 = t & 31;
    const int nn0 = t >> 5;
    const ull ALPHA2 = pack2(0.1f, 0.1f);

    ull hh[8];
    #pragma unroll
    for (int p = 0; p < 8; p++)
        hh[p] = *(const ull*)(H + ((size_t)b * NN + n0 + p * 8 + nn0) * D_ + dq2 * 2);

    #pragma unroll 1
    for (int ol = 0; ol < 6; ol++) {
        ull vv[M_];
        const float* vb = val_sh + ol * (M_ * D_) + dq2 * 2;
        #pragma unroll
        for (int m = 0; m < M_; m++) vv[m] = *(const ull*)(vb + m * D_);

        const float* atb = at_sh + ol * 64 * M_;
        float* ob = out + ((size_t)(ob0 + ol) * NN + n0) * D_ + dq2 * 2;
        #pragma unroll
        for (int p = 0; p < 8; p++) {
            const int nn = p * 8 + nn0;
            const float4* ap = (const float4*)(atb + nn * M_);
            float4 u0 = ap[0], u1 = ap[1], u2 = ap[2];
            ull acc = 0ull;
            acc = ffma2(pack2(u0.x, u0.x), vv[0],  acc);
            acc = ffma2(pack2(u0.y, u0.y), vv[1],  acc);
            acc = ffma2(pack2(u0.z, u0.z), vv[2],  acc);
            acc = ffma2(pack2(u0.w, u0.w), vv[3],  acc);
            acc = ffma2(pack2(u1.x, u1.x), vv[4],  acc);
            acc = ffma2(pack2(u1.y, u1.y), vv[5],  acc);
            acc = ffma2(pack2(u1.z, u1.z), vv[6],  acc);
            acc = ffma2(pack2(u1.w, u1.w), vv[7],  acc);
            acc = ffma2(pack2(u2.x, u2.x), vv[8],  acc);
            acc = ffma2(pack2(u2.y, u2.y), vv[9],  acc);
            acc = ffma2(pack2(u2.z, u2.z), vv[10], acc);
            acc = ffma2(pack2(u2.w, u2.w), vv[11], acc);
            *(ull*)(ob + (size_t)nn * D_) = ffma2(acc, ALPHA2, hh[p]);
        }
    }
}

// ============================================================================
extern "C" void kernel_launch(void* const* d_in, const int* in_sizes, int n_in,
                              void* d_out, int out_size) {
    const float* H        = (const float*)d_in[0];
    const float* ts_out   = (const float*)d_in[1];
    const float* step_emb = (const float*)d_in[2];
    const float* key_emb  = (const float*)d_in[3];
    const float* val_emb  = (const float*)d_in[4];
    const float* Wk       = (const float*)d_in[5];
    const float* Wg       = (const float*)d_in[6];
    const float* bg       = (const float*)d_in[7];
    const float* Wq       = (const float*)d_in[8];
    const float* bq       = (const float*)d_in[9];
    float* out = (float*)d_out;

    prep_kernel<<<dim3(33, B_), 256>>>(H, ts_out, step_emb, key_emb, val_emb,
                                       Wk, Wg, bg, bq, Wq, out);

    const int smem_bytes = SMEM_FLOATS * 4;  // 55584 B
    cudaFuncSetAttribute(attn_kernel, cudaFuncAttributeMaxDynamicSharedMemorySize,
                         smem_bytes);
    attn_kernel<<<dim3(NN / 64, 2, B_), 256, smem_bytes>>>(H, out);
}

// round 12
// speedup vs baseline: 1.2159x; 1.0383x over previous
#include <cuda_runtime.h>
#include <math.h>

// Problem constants
#define B_  16
#define NN  4096
#define D_  64
#define O_  12
#define S_  32
#define M_  12
#define A_  32

// Output layout: H_time [B,O,N,D] ++ attn [B,O,N,M] ++ gate [B,O,M]
#define ATT_OFF  50331648ull
#define GATE_OFF 59768832ull
#define SCALE 0.17677669529663688f   // 1/sqrt(32)

#define QSTRIDE 36   // qh row stride in floats: 9x16B -> LDS.128-aligned, conflict-free

// Scratch
__device__ float g_key[B_*O_*A_*M_];      // [b][o][a][m]
__device__ float g_val[B_*O_*M_*D_];      // [b][o][m][d]  (gate folded in)
__device__ float g_c  [B_*O_*M_];         // [b][o][m]     (qs . key)
__device__ float g_Q  [(size_t)B_*NN*A_]; // [b][n][a]

typedef unsigned long long ull;

__device__ __forceinline__ ull ffma2(ull a, ull b, ull c) {
    ull d;
    asm("fma.rn.f32x2 %0, %1, %2, %3;" : "=l"(d) : "l"(a), "l"(b), "l"(c));
    return d;
}
__device__ __forceinline__ ull pack2(float x, float y) {
    ull r;
    asm("mov.b64 %0, {%1, %2};" : "=l"(r) : "r"(__float_as_uint(x)), "r"(__float_as_uint(y)));
    return r;
}
__device__ __forceinline__ float2 unpack2(ull v) {
    unsigned int lo, hi;
    asm("mov.b64 {%0, %1}, %2;" : "=r"(lo), "=r"(hi) : "l"(v));
    return make_float2(__uint_as_float(lo), __uint_as_float(hi));
}

// ============================================================================
// Kernel 1 (fused prep):
//   bx <  32 : qh (split-D, 2 threads/n)
//   bx >= 32 : precompute for SINGLE o = bx - 32  (parallel over (b,o))
// ============================================================================
__global__ __launch_bounds__(256)
void prep_kernel(const float* __restrict__ H,
                 const float* __restrict__ ts_out,
                 const float* __restrict__ step_emb,
                 const float* __restrict__ key_emb,
                 const float* __restrict__ val_emb,
                 const float* __restrict__ Wk,
                 const float* __restrict__ Wg,
                 const float* __restrict__ bg,
                 const float* __restrict__ bq,
                 const float* __restrict__ Wq,
                 float* __restrict__ out) {
    __shared__ float ps[2560];
    const int b = blockIdx.y;
    const int t = threadIdx.x;

    if (blockIdx.x < 32) {
        // ---------------- qh: 2 threads per n, split D ----------------
        // wq layout: [a] stride 72 floats; half0 at +0 (d=0..31), half1 at +36 (d=32..63)
        for (int i = t; i < 2048; i += 256) {
            const int a = i >> 6, d = i & 63;
            ps[a * 72 + ((d >= 32) ? (4 + d) : d)] = Wq[a * (D_ + S_) + d];
        }
        __syncthreads();

        const int nl   = t >> 1;
        const int half = t & 1;
        const int n    = blockIdx.x * 128 + nl;

        // H half-row: 32 floats -> 16 packed pairs
        const float4* Hp = (const float4*)(H + ((size_t)b * NN + n) * D_ + half * 32);
        ull hp[16];
        #pragma unroll
        for (int i = 0; i < 8; i++) {
            float4 v = Hp[i];
            hp[2 * i]     = pack2(v.x, v.y);
            hp[2 * i + 1] = pack2(v.z, v.w);
        }

        float qh[A_];
        #pragma unroll
        for (int a = 0; a < A_; a++) {
            const ulonglong2* wr = (const ulonglong2*)(ps + a * 72 + half * 36);
            ull acc = 0ull;
            #pragma unroll
            for (int j = 0; j < 8; j++) {           // pairs (2j, 2j+1) of this half
                ulonglong2 w = wr[j];
                acc = ffma2(hp[2 * j],     w.x, acc);
                acc = ffma2(hp[2 * j + 1], w.y, acc);
            }
            float2 f = unpack2(acc);
            const float part = f.x + f.y;
            qh[a] = part + __shfl_xor_sync(0xffffffffu, part, 1);
        }

        // even thread stores a[0..15], odd stores a[16..31] -> warp = 4KB contiguous
        float4* Qo = (float4*)(g_Q + ((size_t)b * NN + n) * A_) + half * 4;
        #pragma unroll
        for (int g = 0; g < 4; g++) {
            const int a0 = half * 16 + g * 4;
            Qo[g] = make_float4(qh[a0], qh[a0 + 1], qh[a0 + 2], qh[a0 + 3]);
        }
    } else {
        // ---------------- precompute: ONE (b, o) per block ----------------
        float* wqs    = ps;           // [a][s] 1024
        float* key_s  = ps + 1024;    // 384
        float* tok_s  = ps + 1408;    // 24
        float* gate_s = ps + 1432;    // 12
        float* qs_s   = ps + 1444;    // 32
        float* step_s = ps + 1476;    // 32

        const int o  = blockIdx.x - 32;
        const int bx = b * O_ + o;

        for (int i = t; i < A_ * S_; i += 256)
            wqs[i] = Wq[(i >> 5) * (D_ + S_) + D_ + (i & 31)];

        if (t < M_) {
            const int m = t;
            const float ph = (m < 8) ? ts_out[bx * 2] : ts_out[bx * 2 + 1];
            const int   k  = (m < 8) ? (m + 1) : (m - 7);
            const float ang = 6.283185307179586477f * ph * (float)k;
            float sn, cs;
            sincosf(ang, &sn, &cs);
            tok_s[2 * m]     = sn;
            tok_s[2 * m + 1] = cs;
            const float g = tanhf(sn * Wg[0] + cs * Wg[1] + bg[0]);
            gate_s[m] = g;
            out[GATE_OFF + (size_t)bx * M_ + m] = g;
        }
        if (t >= 32 && t < 64) step_s[t - 32] = step_emb[bx * S_ + t - 32];
        __syncthreads();

        for (int i = t; i < A_ * M_; i += 256) {
            const int a = i / 12, m = i - a * 12;
            const float kv = tok_s[2 * m] * Wk[2 * a] + tok_s[2 * m + 1] * Wk[2 * a + 1]
                           + key_emb[m * A_ + a];
            key_s[i] = kv;
            g_key[(size_t)bx * (A_ * M_) + i] = kv;
        }
        for (int i = t; i < M_ * D_; i += 256)
            g_val[(size_t)bx * (M_ * D_) + i] = gate_s[i >> 6] * val_emb[i];
        if (t < A_) {
            float acc = bq[t];
            #pragma unroll
            for (int s = 0; s < S_; s++) acc += step_s[s] * wqs[t * S_ + s];
            qs_s[t] = acc;
        }
        __syncthreads();

        if (t < M_) {
            float acc = 0.f;
            #pragma unroll
            for (int a = 0; a < A_; a++) acc += qs_s[a] * key_s[a * 12 + t];
            g_c[(size_t)bx * M_ + t] = acc;
        }
    }
}

// ============================================================================
// Kernel 2: main. Block = 64 n x 6 o (o-half), 256 threads.
//   smem (floats): key 2304 | val 4608 | c 72 | at 4608 | qh 64*36=2304
// ============================================================================
#define SMEM_FLOATS 13896

__global__ __launch_bounds__(256, 4)
void attn_kernel(const float* __restrict__ H, float* __restrict__ out) {
    extern __shared__ float sh[];
    float* key_sh = sh;             // [ol][a][m]  2304
    float* val_sh = sh + 2304;      // [ol][m][d]  4608
    float* c_sh   = sh + 6912;      // [ol][m] 72
    float* at_sh  = sh + 6984;      // [ol*64+nl][m] 4608
    float* qh_sh  = sh + 11592;     // [nl][a] stride QSTRIDE

    const int t   = threadIdx.x;
    const int b   = blockIdx.z;
    const int oh  = blockIdx.y;
    const int n0  = blockIdx.x * 64;
    const int ob0 = b * O_ + oh * 6;

    // ---- stage tables (coalesced) ----
    {
        const float4* gk = (const float4*)(g_key + (size_t)ob0 * (A_ * M_));
        float4* k4 = (float4*)key_sh;
        for (int i = t; i < 576; i += 256) k4[i] = gk[i];
        const float4* gv = (const float4*)(g_val + (size_t)ob0 * (M_ * D_));
        float4* v4 = (float4*)val_sh;
        for (int i = t; i < 1152; i += 256) v4[i] = gv[i];
        if (t < 72) c_sh[t] = g_c[(size_t)ob0 * M_ + t];
        // Q tile via float4: row = i>>3, col4 = i&7
        const float4* Qb = (const float4*)(g_Q + ((size_t)b * NN + n0) * A_);
        for (int i = t; i < 512; i += 256) {
            float4 v = Qb[i];
            *(float4*)(qh_sh + (i >> 3) * QSTRIDE + (i & 7) * 4) = v;
        }
    }
    __syncthreads();

    // ---- phase A: job = (nl, ol); logits, softmax -> at_sh ----
    for (int j = t; j < 384; j += 256) {
        const int nl = j & 63;
        const int ol = j >> 6;

        ull lg[6];
        const float* cp = c_sh + ol * M_;
        #pragma unroll
        for (int p = 0; p < 6; p++) lg[p] = pack2(cp[2 * p], cp[2 * p + 1]);

        float qh[A_];
        {
            const float4* qp4 = (const float4*)(qh_sh + nl * QSTRIDE);
            #pragma unroll
            for (int q = 0; q < 8; q++) {
                float4 v = qp4[q];
                qh[4*q] = v.x; qh[4*q+1] = v.y; qh[4*q+2] = v.z; qh[4*q+3] = v.w;
            }
        }
        const float* kp = key_sh + ol * (A_ * M_);
        #pragma unroll
        for (int a = 0; a < A_; a++) {
            const ull q2 = pack2(qh[a], qh[a]);
            const ulonglong2* kr = (const ulonglong2*)(kp + a * M_);
            ulonglong2 k0 = kr[0], k1 = kr[1], k2 = kr[2];
            lg[0] = ffma2(q2, k0.x, lg[0]);
            lg[1] = ffma2(q2, k0.y, lg[1]);
            lg[2] = ffma2(q2, k1.x, lg[2]);
            lg[3] = ffma2(q2, k1.y, lg[3]);
            lg[4] = ffma2(q2, k2.x, lg[4]);
            lg[5] = ffma2(q2, k2.y, lg[5]);
        }
        float l[M_];
        #pragma unroll
        for (int p = 0; p < 6; p++) {
            float2 f = unpack2(lg[p]);
            l[2 * p] = f.x; l[2 * p + 1] = f.y;
        }
        float mx = l[0];
        #pragma unroll
        for (int m = 1; m < M_; m++) mx = fmaxf(mx, l[m]);
        float ssum = 0.f, at[M_];
        #pragma unroll
        for (int m = 0; m < M_; m++) {
            const float e = __expf((l[m] - mx) * SCALE);
            at[m] = e; ssum += e;
        }
        const float inv = __frcp_rn(ssum);
        #pragma unroll
        for (int m = 0; m < M_; m++) at[m] *= inv;

        float4* as = (float4*)(at_sh + (ol * 64 + nl) * M_);
        as[0] = make_float4(at[0], at[1], at[2],  at[3]);
        as[1] = make_float4(at[4], at[5], at[6],  at[7]);
        as[2] = make_float4(at[8], at[9], at[10], at[11]);
    }
    __syncthreads();

    // ---- attn output: coalesced copy at_sh -> global ----
    if (t < 192) {
        #pragma unroll
        for (int ol = 0; ol < 6; ol++) {
            float4 v = *(const float4*)(at_sh + ol * 768 + t * 4);
            *(float4*)(out + ATT_OFF + ((size_t)(ob0 + ol) * NN + n0) * M_ + t * 4) = v;
        }
    }

    // ---- phase B: thread = (dq2 8B-chunk, nn0); val hoisted per o ----
    const int dq2 = t & 31;
    const int nn0 = t >> 5;
    const ull ALPHA2 = pack2(0.1f, 0.1f);

    ull hh[8];
    #pragma unroll
    for (int p = 0; p < 8; p++)
        hh[p] = *(const ull*)(H + ((size_t)b * NN + n0 + p * 8 + nn0) * D_ + dq2 * 2);

    #pragma unroll 1
    for (int ol = 0; ol < 6; ol++) {
        ull vv[M_];
        const float* vb = val_sh + ol * (M_ * D_) + dq2 * 2;
        #pragma unroll
        for (int m = 0; m < M_; m++) vv[m] = *(const ull*)(vb + m * D_);

        const float* atb = at_sh + ol * 64 * M_;
        float* ob = out + ((size_t)(ob0 + ol) * NN + n0) * D_ + dq2 * 2;
        #pragma unroll
        for (int p = 0; p < 8; p++) {
            const int nn = p * 8 + nn0;
            const float4* ap = (const float4*)(atb + nn * M_);
            float4 u0 = ap[0], u1 = ap[1], u2 = ap[2];
            ull acc = 0ull;
            acc = ffma2(pack2(u0.x, u0.x), vv[0],  acc);
            acc = ffma2(pack2(u0.y, u0.y), vv[1],  acc);
            acc = ffma2(pack2(u0.z, u0.z), vv[2],  acc);
            acc = ffma2(pack2(u0.w, u0.w), vv[3],  acc);
            acc = ffma2(pack2(u1.x, u1.x), vv[4],  acc);
            acc = ffma2(pack2(u1.y, u1.y), vv[5],  acc);
            acc = ffma2(pack2(u1.z, u1.z), vv[6],  acc);
            acc = ffma2(pack2(u1.w, u1.w), vv[7],  acc);
            acc = ffma2(pack2(u2.x, u2.x), vv[8],  acc);
            acc = ffma2(pack2(u2.y, u2.y), vv[9],  acc);
            acc = ffma2(pack2(u2.z, u2.z), vv[10], acc);
            acc = ffma2(pack2(u2.w, u2.w), vv[11], acc);
            *(ull*)(ob + (size_t)nn * D_) = ffma2(acc, ALPHA2, hh[p]);
        }
    }
}

// ============================================================================
extern "C" void kernel_launch(void* const* d_in, const int* in_sizes, int n_in,
                              void* d_out, int out_size) {
    const float* H        = (const float*)d_in[0];
    const float* ts_out   = (const float*)d_in[1];
    const float* step_emb = (const float*)d_in[2];
    const float* key_emb  = (const float*)d_in[3];
    const float* val_emb  = (const float*)d_in[4];
    const float* Wk       = (const float*)d_in[5];
    const float* Wg       = (const float*)d_in[6];
    const float* bg       = (const float*)d_in[7];
    const float* Wq       = (const float*)d_in[8];
    const float* bq       = (const float*)d_in[9];
    float* out = (float*)d_out;

    prep_kernel<<<dim3(32 + O_, B_), 256>>>(H, ts_out, step_emb, key_emb, val_emb,
                                            Wk, Wg, bg, bq, Wq, out);

    const int smem_bytes = SMEM_FLOATS * 4;  // 55584 B
    cudaFuncSetAttribute(attn_kernel, cudaFuncAttributeMaxDynamicSharedMemorySize,
                         smem_bytes);
    attn_kernel<<<dim3(NN / 64, 2, B_), 256, smem_bytes>>>(H, out);
}